// round 16
// baseline (speedup 1.0000x reference)
#include <cuda_runtime.h>
#include <math.h>

// Problem constants
constexpr int kB = 256, kN = 1152, kD = 8, kO = 10, kE = 16;
constexpr int kOE = kO * kE;  // 160

// Persistent fused kernel: 288 blocks (144 n-groups x 2 batch halves),
// 320 threads, 2 CTAs/SM -> all blocks co-resident (288 <= 296).
constexpr int kNL    = 8;
constexpr int kTH    = 320;       // tid = nl(b0-2) + eg(b3-4) + o(b5+)
constexpr int kNG    = kN / kNL;  // 144
constexpr int kGrid  = kNG * 2;   // 288
constexpr int kBH    = kB / 2;    // 128 batches per block
constexpr int kCB0   = 8;         // MODE0 chunk
constexpr int kNCH0  = kBH / kCB0;   // 16
constexpr int kCB1   = 4;         // MODE1 chunk (pipelined)
constexpr int kNCH1  = kBH / kCB1;   // 32

// SMEM (floats)
constexpr int kUSd  = kBH;                    // 128
constexpr int kUSnl = kD * kUSd + 4;          // 1028
constexpr int kOffL = kNL * kUSnl;            // 8224
// logits buffer (per chunk): [nl][kp(2)][o*2]; triple-buffered
constexpr int kLSbp = 20;
constexpr int kLSnl = 2 * kLSbp + 4;          // 44 (nl bank offset 12: distinct)
constexpr int kLBuf = kNL * kLSnl;            // 352
constexpr int kSmemFloats = kOffL + 3 * kLBuf;  // 9280
constexpr int kSmemBytes  = kSmemFloats * 4;    // 37120 (x2 CTA = 74KB)

typedef unsigned long long u64;

__device__ float g_part[(size_t)kNG * kB * kOE];  // 23.6 MB
__device__ float g_vsum[kB * kOE];
__device__ unsigned g_bar;  // monotonic ticket barrier (never reset)

#define FMA2(d, a, b_) asm("fma.rn.f32x2 %0, %1, %2, %0;" : "+l"(d) : "l"(a), "l"(b_))
#define MUL2(d, a, b_) asm("mul.rn.f32x2 %0, %1, %2;" : "=l"(d) : "l"(a), "l"(b_))
#define ADD2(d, a, b_) asm("add.rn.f32x2 %0, %1, %2;" : "=l"(d) : "l"(a), "l"(b_))
#define PACK2(d, lo, hi) \
  asm("mov.b64 %0, {%1, %2};" : "=l"(d) : "r"(__float_as_uint(lo)), "r"(__float_as_uint(hi)))
#define UNPK2(lo, hi, v)                                                \
  do {                                                                  \
    unsigned _l, _h;                                                    \
    asm("mov.b64 {%0, %1}, %2;" : "=r"(_l), "=r"(_h) : "l"(v));         \
    lo = __uint_as_float(_l); hi = __uint_as_float(_h);                 \
  } while (0)

// Grid-wide barrier: ticket-based, monotonic counter (graph-replay safe).
__device__ __forceinline__ void grid_barrier(int tid) {
  __syncthreads();
  if (tid == 0) {
    __threadfence();
    unsigned t = atomicAdd(&g_bar, 1u);
    unsigned target = (t / (unsigned)kGrid + 1u) * (unsigned)kGrid;
    while (*(volatile unsigned*)&g_bar < target) __nanosleep(64);
  }
  __syncthreads();
}

// ---------- MODE 0 helpers (8-batch chunks, no barriers) ----------

__device__ __forceinline__ void compute_acc8(
    u64 acc[4][4], const float* __restrict__ up, const float w[kD][4], u64 bp)
{
#pragma unroll
  for (int k = 0; k < 4; k++)
#pragma unroll
    for (int j = 0; j < 4; j++) acc[k][j] = bp;
#pragma unroll
  for (int d = 0; d < kD; d++) {
    ulonglong2 ua = *(const ulonglong2*)(up + d * kUSd);
    ulonglong2 ub = *(const ulonglong2*)(up + d * kUSd + 4);
    u64 w2[4];
    PACK2(w2[0], w[d][0], w[d][0]); PACK2(w2[1], w[d][1], w[d][1]);
    PACK2(w2[2], w[d][2], w[d][2]); PACK2(w2[3], w[d][3], w[d][3]);
    FMA2(acc[0][0], ua.x, w2[0]); FMA2(acc[0][1], ua.x, w2[1]);
    FMA2(acc[0][2], ua.x, w2[2]); FMA2(acc[0][3], ua.x, w2[3]);
    FMA2(acc[1][0], ua.y, w2[0]); FMA2(acc[1][1], ua.y, w2[1]);
    FMA2(acc[1][2], ua.y, w2[2]); FMA2(acc[1][3], ua.y, w2[3]);
    FMA2(acc[2][0], ub.x, w2[0]); FMA2(acc[2][1], ub.x, w2[1]);
    FMA2(acc[2][2], ub.x, w2[2]); FMA2(acc[2][3], ub.x, w2[3]);
    FMA2(acc[3][0], ub.y, w2[0]); FMA2(acc[3][1], ub.y, w2[1]);
    FMA2(acc[3][2], ub.y, w2[2]); FMA2(acc[3][3], ub.y, w2[3]);
  }
}

__device__ __forceinline__ void pass_phase0(
    float* u_s, int tid, int nl, int eg, int o,
    int bb0, int ng, const float w[kD][4], u64 bp)
{
  const float* up_base = u_s + nl * kUSnl;
  const int mm = ((nl >> 2) & 1) * 8 + ((nl >> 1) & 1) * 4 + (nl & 1) * 2;
  const int kk = mm >> 2, j0 = mm & 3;

  for (int ch = 0; ch < kNCH0; ch++) {
    const int bc  = ch * kCB0;
    const int bca = bb0 + bc;
    u64 acc[4][4];
    compute_acc8(acc, up_base + bc, w, bp);

    // reduce-scatter over nl (lane bits 0-2): 3 levels on 16 u64 -> 2
    u64 v8[8];
    {
      const bool sel = (nl >> 2) & 1;
#pragma unroll
      for (int i = 0; i < 8; i++) {
        u64 send = sel ? acc[i >> 2][i & 3] : acc[2 + (i >> 2)][i & 3];
        u64 recv = __shfl_xor_sync(0xffffffffu, send, 4);
        u64 keep = sel ? acc[2 + (i >> 2)][i & 3] : acc[i >> 2][i & 3];
        ADD2(v8[i], keep, recv);
      }
    }
    u64 v4[4];
    {
      const bool sel = (nl >> 1) & 1;
#pragma unroll
      for (int i = 0; i < 4; i++) {
        u64 send = sel ? v8[i] : v8[4 + i];
        u64 recv = __shfl_xor_sync(0xffffffffu, send, 2);
        u64 keep = sel ? v8[4 + i] : v8[i];
        ADD2(v4[i], keep, recv);
      }
    }
    u64 v2[2];
    {
      const bool sel = nl & 1;
#pragma unroll
      for (int i = 0; i < 2; i++) {
        u64 send = sel ? v4[i] : v4[2 + i];
        u64 recv = __shfl_xor_sync(0xffffffffu, send, 1);
        u64 keep = sel ? v4[2 + i] : v4[i];
        ADD2(v2[i], keep, recv);
      }
    }
    float l0, h0, l1, h1;
    UNPK2(l0, h0, v2[0]); UNPK2(l1, h1, v2[1]);
    float* dp = &g_part[((size_t)ng * kB + bca + 2 * kk) * kOE
                        + o * kE + eg * 4 + j0];
    *(float2*)dp         = make_float2(l0, l1);
    *(float2*)(dp + kOE) = make_float2(h0, h1);
  }
}

// ---------- MODE 1 helpers (4-batch chunks, pipelined softmax) ----------

__device__ __forceinline__ void compute_acc4(
    u64 acc[2][4], const float* __restrict__ up, const float w[kD][4], u64 bp)
{
#pragma unroll
  for (int k = 0; k < 2; k++)
#pragma unroll
    for (int j = 0; j < 4; j++) acc[k][j] = bp;
#pragma unroll
  for (int d = 0; d < kD; d++) {
    ulonglong2 ua = *(const ulonglong2*)(up + d * kUSd);  // bpairs (b0,b1),(b2,b3)
    u64 w2[4];
    PACK2(w2[0], w[d][0], w[d][0]); PACK2(w2[1], w[d][1], w[d][1]);
    PACK2(w2[2], w[d][2], w[d][2]); PACK2(w2[3], w[d][3], w[d][3]);
    FMA2(acc[0][0], ua.x, w2[0]); FMA2(acc[0][1], ua.x, w2[1]);
    FMA2(acc[0][2], ua.x, w2[2]); FMA2(acc[0][3], ua.x, w2[3]);
    FMA2(acc[1][0], ua.y, w2[0]); FMA2(acc[1][1], ua.y, w2[1]);
    FMA2(acc[1][2], ua.y, w2[2]); FMA2(acc[1][3], ua.y, w2[3]);
  }
}

__device__ __forceinline__ void logits4(
    const u64 acc[2][4], int bca, float* lb, int nl, int eg, int o)
{
  u64 ag[2] = {0ull, 0ull};
#pragma unroll
  for (int kp = 0; kp < 2; kp++) {
    const float* vp0 = g_vsum + (size_t)(bca + 2 * kp) * kOE + o * kE + eg * 4;
    float4 va = __ldcg((const float4*)vp0);
    float4 vb = __ldcg((const float4*)(vp0 + kOE));
    u64 t;
    PACK2(t, va.x, vb.x); FMA2(ag[kp], acc[kp][0], t);
    PACK2(t, va.y, vb.y); FMA2(ag[kp], acc[kp][1], t);
    PACK2(t, va.z, vb.z); FMA2(ag[kp], acc[kp][2], t);
    PACK2(t, va.w, vb.w); FMA2(ag[kp], acc[kp][3], t);
  }
#pragma unroll
  for (int kp = 0; kp < 2; kp++) {
    u64 r = __shfl_xor_sync(0xffffffffu, ag[kp], 8);
    ADD2(ag[kp], ag[kp], r);
    r = __shfl_xor_sync(0xffffffffu, ag[kp], 16);
    ADD2(ag[kp], ag[kp], r);
  }
  if (eg == 0) {
    float* ar = lb + nl * kLSnl + o * 2;
    *(u64*)ar           = ag[0];
    *(u64*)(ar + kLSbp) = ag[1];
  }
}

__device__ __forceinline__ void softmax4(float* lb, int tid) {
  // 16 pair-rows: (nl = tid>>1, kp = tid&1)
  float* row = lb + (tid >> 1) * kLSnl + (tid & 1) * kLSbp;
  float ex[kO], ey[kO];
  float sx = 0.f, sy = 0.f;
#pragma unroll
  for (int q = 0; q < kO; q++) {
    float2 t = *(const float2*)(row + q * 2);
    ex[q] = __expf(t.x); ey[q] = __expf(t.y);
    sx += ex[q]; sy += ey[q];
  }
  float ix = 1.f / sx, iy = 1.f / sy;
#pragma unroll
  for (int q = 0; q < kO; q++)
    *(float2*)(row + q * 2) = make_float2(ex[q] * ix, ey[q] * iy);
}

__device__ __forceinline__ void phaseC4(
    const u64 acc[2][4], const float* lb, int bca, int ng,
    int nl, int eg, int o, int kp_, int j_)
{
  const float* cp = lb + nl * kLSnl + o * 2;
  u64 c0 = *(const u64*)cp;
  u64 c1 = *(const u64*)(cp + kLSbp);
  u64 v8[8];
#pragma unroll
  for (int j = 0; j < 4; j++) {
    MUL2(v8[j],     acc[0][j], c0);
    MUL2(v8[4 + j], acc[1][j], c1);
  }
  // reduce-scatter over nl (lane bits 0-2): 3 levels, 8 -> 1
  u64 v4[4];
  {
    const bool sel = (nl >> 2) & 1;
#pragma unroll
    for (int i = 0; i < 4; i++) {
      u64 send = sel ? v8[i] : v8[4 + i];
      u64 recv = __shfl_xor_sync(0xffffffffu, send, 4);
      u64 keep = sel ? v8[4 + i] : v8[i];
      ADD2(v4[i], keep, recv);
    }
  }
  u64 v2[2];
  {
    const bool sel = (nl >> 1) & 1;
#pragma unroll
    for (int i = 0; i < 2; i++) {
      u64 send = sel ? v2[0] : v2[0];  // placeholder avoided below
      (void)send;
      u64 s2 = sel ? v4[i] : v4[2 + i];
      u64 recv = __shfl_xor_sync(0xffffffffu, s2, 2);
      u64 keep = sel ? v4[2 + i] : v4[i];
      ADD2(v2[i], keep, recv);
    }
  }
  u64 v1;
  {
    const bool sel = nl & 1;
    u64 s2 = sel ? v2[0] : v2[1];
    u64 recv = __shfl_xor_sync(0xffffffffu, s2, 1);
    u64 keep = sel ? v2[1] : v2[0];
    ADD2(v1, keep, recv);
  }
  float lo, hi;
  UNPK2(lo, hi, v1);
  float* dp = &g_part[((size_t)ng * kB + bca + 2 * kp_) * kOE
                      + o * kE + eg * 4 + j_];
  dp[0]   = lo;
  dp[kOE] = hi;
}

__device__ __forceinline__ void pass_phase1(
    float* u_s, float* l_s, int tid, int nl, int eg, int o,
    int bb0, int ng, const float w[kD][4], u64 bp)
{
  const float* up_base = u_s + nl * kUSnl;
  const int kp_ = nl >> 2, j_ = nl & 3;  // final scatter index (idx == nl)

  u64 accP[2][4];
  int prevBca;
  int bi = 0;

  // chunk 0
  compute_acc4(accP, up_base, w, bp);
  logits4(accP, bb0, l_s, nl, eg, o);
  prevBca = bb0;
  __syncthreads();
  if (tid < 16) softmax4(l_s, tid);

  int biPrev = 0;
  bi = 1;
  for (int ci = 1; ci < kNCH1; ci++) {
    const int bc  = ci * kCB1;
    const int bca = bb0 + bc;
    u64 accN[2][4];
    compute_acc4(accN, up_base + bc, w, bp);
    logits4(accN, bca, l_s + bi * kLBuf, nl, eg, o);
    __syncthreads();  // logits(ci) visible; softmax(ci-1) results visible
    if (tid < 16) softmax4(l_s + bi * kLBuf, tid);
    phaseC4(accP, l_s + biPrev * kLBuf, prevBca, ng, nl, eg, o, kp_, j_);
#pragma unroll
    for (int k = 0; k < 2; k++)
#pragma unroll
      for (int j = 0; j < 4; j++) accP[k][j] = accN[k][j];
    prevBca = bca;
    biPrev = bi;
    bi = (bi == 2) ? 0 : bi + 1;
  }
  __syncthreads();  // softmax(last) visible
  phaseC4(accP, l_s + biPrev * kLBuf, prevBca, ng, nl, eg, o, kp_, j_);
}

// Reduce 144 partials + squash. 40960 items = blocks 0..127 exactly.
__device__ __forceinline__ void squash_phase(float* __restrict__ out,
                                             int mode, float scale, int tid) {
  if (blockIdx.x >= 128) return;
  int gt = blockIdx.x * kTH + tid;
  int h = gt & 3, eq = (gt >> 2) & 3, row = gt >> 4;  // row = b*10 + o
  const float* pp = g_part + (size_t)row * kE + eq * 4
                  + (size_t)(h * 36) * kB * kOE;
  float4 a = {0.f, 0.f, 0.f, 0.f};
#pragma unroll 4
  for (int p = 0; p < 36; p++) {
    float4 t = __ldcg((const float4*)(pp + (size_t)p * kB * kOE));
    a.x += t.x; a.y += t.y; a.z += t.z; a.w += t.w;
  }
  a.x += __shfl_xor_sync(0xffffffffu, a.x, 1);
  a.y += __shfl_xor_sync(0xffffffffu, a.y, 1);
  a.z += __shfl_xor_sync(0xffffffffu, a.z, 1);
  a.w += __shfl_xor_sync(0xffffffffu, a.w, 1);
  a.x += __shfl_xor_sync(0xffffffffu, a.x, 2);
  a.y += __shfl_xor_sync(0xffffffffu, a.y, 2);
  a.z += __shfl_xor_sync(0xffffffffu, a.z, 2);
  a.w += __shfl_xor_sync(0xffffffffu, a.w, 2);
  a.x *= scale; a.y *= scale; a.z *= scale; a.w *= scale;
  float n2 = a.x * a.x + a.y * a.y + a.z * a.z + a.w * a.w;
  n2 += __shfl_xor_sync(0xffffffffu, n2, 4);
  n2 += __shfl_xor_sync(0xffffffffu, n2, 8);
  float f = sqrtf(n2) / (1.f + n2);
  float4 v = make_float4(a.x * f, a.y * f, a.z * f, a.w * f);
  if (h == 0) {
    if (mode == 2) {
      *(float4*)(out + (size_t)row * kE + eq * 4) = v;
    } else if (mode == 1) {
      float4 old = *(const float4*)(g_vsum + (size_t)row * kE + eq * 4);
      v.x += old.x; v.y += old.y; v.z += old.z; v.w += old.w;
      *(float4*)(g_vsum + (size_t)row * kE + eq * 4) = v;
    } else {
      *(float4*)(g_vsum + (size_t)row * kE + eq * 4) = v;
    }
  }
}

__global__ void __launch_bounds__(kTH, 2) fused_kernel(
    const float* __restrict__ u_i,
    const float* __restrict__ W,
    const float* __restrict__ bias,
    float* __restrict__ out)
{
  extern __shared__ float sm[];
  float* u_s = sm;            // [nl(1028)][d(128)][b]
  float* l_s = sm + kOffL;    // 3 x [nl(44)][kp(20)] logits/c buffers

  const int tid = threadIdx.x;
  const int nl  = tid & 7;
  const int eg  = (tid >> 3) & 3;
  const int o   = tid >> 5;
  const int ng  = blockIdx.x >> 1;
  const int n0  = ng * kNL;
  const int bb0 = (blockIdx.x & 1) * kBH;

  // W slice + bias, once for all 3 iterations
  float w[kD][4];
  {
    const float* Wp = W + ((size_t)(n0 + nl) * kO + o) * (kD * kE) + eg * 4;
#pragma unroll
    for (int d = 0; d < kD; d++) {
      float4 w4 = *(const float4*)(Wp + d * kE);
      w[d][0] = w4.x; w[d][1] = w4.y; w[d][2] = w4.z; w[d][3] = w4.w;
    }
  }
  const float bv = bias[(n0 + nl) * kO + o];
  u64 bp; PACK2(bp, bv, bv);

  // stage u once for all 3 iterations: [b][n][d] -> [nl][d][b_local]
  for (int i = tid; i < kBH * kNL * 2; i += kTH) {
    int b = i >> 4, nl2 = (i >> 1) & 7, h = i & 1;
    float4 t = *(const float4*)(u_i + ((size_t)(bb0 + b) * kN + n0 + nl2) * kD + h * 4);
    float* du = u_s + nl2 * kUSnl + h * 4 * kUSd + b;
    du[0] = t.x; du[kUSd] = t.y; du[2 * kUSd] = t.z; du[3 * kUSd] = t.w;
  }
  __syncthreads();

  // iteration 1: uniform c (0.1 folded into squash scale)
  pass_phase0(u_s, tid, nl, eg, o, bb0, ng, w, bp);
  grid_barrier(tid);
  squash_phase(out, 0, 0.1f, tid);   // g_vsum = v1
  grid_barrier(tid);

  // iteration 2
  pass_phase1(u_s, l_s, tid, nl, eg, o, bb0, ng, w, bp);
  grid_barrier(tid);
  squash_phase(out, 1, 1.0f, tid);   // g_vsum = v1 + v2
  grid_barrier(tid);

  // iteration 3
  pass_phase1(u_s, l_s, tid, nl, eg, o, bb0, ng, w, bp);
  grid_barrier(tid);
  squash_phase(out, 2, 1.0f, tid);   // out = v3
}

extern "C" void kernel_launch(void* const* d_in, const int* in_sizes, int n_in,
                              void* d_out, int out_size) {
  const float* u    = (const float*)d_in[0];
  const float* W    = (const float*)d_in[1];
  const float* bias = (const float*)d_in[2];
  float* out = (float*)d_out;

  cudaFuncSetAttribute((const void*)fused_kernel,
                       cudaFuncAttributeMaxDynamicSharedMemorySize, kSmemBytes);

  fused_kernel<<<kGrid, kTH, kSmemBytes>>>(u, W, bias, out);
}

// round 17
// speedup vs baseline: 1.1528x; 1.1528x over previous
#include <cuda_runtime.h>
#include <math.h>

// Problem constants
constexpr int kB = 256, kN = 1152, kD = 8, kO = 10, kE = 16;
constexpr int kOE = kO * kE;  // 160

// Persistent fused kernel: 288 blocks (144 n-groups x 2 batch halves),
// 320 threads, 2 CTAs/SM -> all blocks co-resident (288 <= 296).
constexpr int kNL   = 8;
constexpr int kTH   = 320;        // tid = nl(b0-2) + eg(b3-4) + o(b5+)
constexpr int kNG   = kN / kNL;   // 144
constexpr int kGrid = kNG * 2;    // 288
constexpr int kBH   = kB / 2;     // 128 batches per block
constexpr int kCB   = 8;
constexpr int kNCH  = kBH / kCB;  // 16 chunks

// SMEM (floats)
constexpr int kUSd  = kBH;                    // 128
constexpr int kUSnl = kD * kUSd + 4;          // 1028
constexpr int kOffL = kNL * kUSnl;            // 8224
constexpr int kLSbp = 20;
constexpr int kLSnl = (kBH / 2) * kLSbp + 4;  // 1284 (mod 32 == 4)
constexpr int kSmemFloats = kOffL + kNL * kLSnl;  // 18496
constexpr int kSmemBytes  = kSmemFloats * 4;      // 73984 (x2 CTA = 148KB)

typedef unsigned long long u64;

__device__ float g_part[(size_t)kNG * kB * kOE];  // 23.6 MB
__device__ float g_vsum[kB * kOE];
__device__ unsigned g_bar;  // monotonic ticket barrier (never reset)

#define FMA2(d, a, b_) asm("fma.rn.f32x2 %0, %1, %2, %0;" : "+l"(d) : "l"(a), "l"(b_))
#define MUL2(d, a, b_) asm("mul.rn.f32x2 %0, %1, %2;" : "=l"(d) : "l"(a), "l"(b_))
#define ADD2(d, a, b_) asm("add.rn.f32x2 %0, %1, %2;" : "=l"(d) : "l"(a), "l"(b_))
#define PACK2(d, lo, hi) \
  asm("mov.b64 %0, {%1, %2};" : "=l"(d) : "r"(__float_as_uint(lo)), "r"(__float_as_uint(hi)))
#define UNPK2(lo, hi, v)                                                \
  do {                                                                  \
    unsigned _l, _h;                                                    \
    asm("mov.b64 {%0, %1}, %2;" : "=r"(_l), "=r"(_h) : "l"(v));         \
    lo = __uint_as_float(_l); hi = __uint_as_float(_h);                 \
  } while (0)

// Grid-wide barrier: ticket-based, monotonic counter (graph-replay safe).
__device__ __forceinline__ void grid_barrier(int tid) {
  __syncthreads();
  if (tid == 0) {
    __threadfence();
    unsigned t = atomicAdd(&g_bar, 1u);
    unsigned target = (t / (unsigned)kGrid + 1u) * (unsigned)kGrid;
    while (*(volatile unsigned*)&g_bar < target) __nanosleep(64);
  }
  __syncthreads();
}

// 4x4 u_ji tile (bias included) for one chunk of 8 batches.
__device__ __forceinline__ void compute_acc(
    u64 acc[4][4], const float* __restrict__ up, const float w[kD][4], u64 bp)
{
#pragma unroll
  for (int k = 0; k < 4; k++)
#pragma unroll
    for (int j = 0; j < 4; j++) acc[k][j] = bp;
#pragma unroll
  for (int d = 0; d < kD; d++) {
    ulonglong2 ua = *(const ulonglong2*)(up + d * kUSd);      // b (0,1),(2,3)
    ulonglong2 ub = *(const ulonglong2*)(up + d * kUSd + 4);  // b (4,5),(6,7)
    u64 w2[4];
    PACK2(w2[0], w[d][0], w[d][0]); PACK2(w2[1], w[d][1], w[d][1]);
    PACK2(w2[2], w[d][2], w[d][2]); PACK2(w2[3], w[d][3], w[d][3]);
    FMA2(acc[0][0], ua.x, w2[0]); FMA2(acc[0][1], ua.x, w2[1]);
    FMA2(acc[0][2], ua.x, w2[2]); FMA2(acc[0][3], ua.x, w2[3]);
    FMA2(acc[1][0], ua.y, w2[0]); FMA2(acc[1][1], ua.y, w2[1]);
    FMA2(acc[1][2], ua.y, w2[2]); FMA2(acc[1][3], ua.y, w2[3]);
    FMA2(acc[2][0], ub.x, w2[0]); FMA2(acc[2][1], ub.x, w2[1]);
    FMA2(acc[2][2], ub.x, w2[2]); FMA2(acc[2][3], ub.x, w2[3]);
    FMA2(acc[3][0], ub.y, w2[0]); FMA2(acc[3][1], ub.y, w2[1]);
    FMA2(acc[3][2], ub.y, w2[2]); FMA2(acc[3][3], ub.y, w2[3]);
  }
}

// One routing pass over this block's 128 batches. acc held across barriers.
// MODE 0: c uniform (0.1 folded into squash).  MODE 1: c = softmax_o(<u_ji, v>).
template <int MODE>
__device__ __forceinline__ void pass_phase(
    float* u_s, float* l_s, int tid, int nl, int eg, int o,
    int bb0, int ng, const float w[kD][4], u64 bp)
{
  const float* up_base = u_s + nl * kUSnl;
  const int mm = ((nl >> 2) & 1) * 8 + ((nl >> 1) & 1) * 4 + (nl & 1) * 2;
  const int kk = mm >> 2, j0 = mm & 3;

  for (int ch = 0; ch < kNCH; ch++) {
    const int bc  = ch * kCB;
    const int bc2 = ch * 4;
    const int bca = bb0 + bc;

    // prefetch v (L1-bypassed: g_vsum is rewritten in-kernel)
    float4 vA[4], vB[4];
    if (MODE) {
#pragma unroll
      for (int k = 0; k < 4; k++) {
        const float* vp0 = g_vsum + (size_t)(bca + 2 * k) * kOE + o * kE + eg * 4;
        vA[k] = __ldcg((const float4*)vp0);
        vB[k] = __ldcg((const float4*)(vp0 + kOE));
      }
    }

    u64 acc[4][4];
    compute_acc(acc, up_base + bc, w, bp);

    if (MODE) {
      u64 ag[4] = {0ull, 0ull, 0ull, 0ull};
#pragma unroll
      for (int k = 0; k < 4; k++) {
        u64 vp;
        PACK2(vp, vA[k].x, vB[k].x); FMA2(ag[k], acc[k][0], vp);
        PACK2(vp, vA[k].y, vB[k].y); FMA2(ag[k], acc[k][1], vp);
        PACK2(vp, vA[k].z, vB[k].z); FMA2(ag[k], acc[k][2], vp);
        PACK2(vp, vA[k].w, vB[k].w); FMA2(ag[k], acc[k][3], vp);
      }
      // eg-reduction (lane bits 3,4), packed u64
#pragma unroll
      for (int k = 0; k < 4; k++) {
        u64 r = __shfl_xor_sync(0xffffffffu, ag[k], 8);
        ADD2(ag[k], ag[k], r);
        r = __shfl_xor_sync(0xffffffffu, ag[k], 16);
        ADD2(ag[k], ag[k], r);
      }
      if (eg == 0) {
        float* ar = l_s + nl * kLSnl + bc2 * kLSbp + o * 2;
#pragma unroll
        for (int k = 0; k < 4; k++)
          *(u64*)(ar + k * kLSbp) = ag[k];
      }
      __syncthreads();

      // pair-softmax, split-row: 64 threads (warps 0+1), each does 5 o's of
      // one of 32 pair-rows; half-sums combined via intra-warp shfl_xor(1).
      if (tid < 64) {
        const int r = tid >> 1;       // pair-row 0..31: nl = r>>2, k = r&3
        const int h = tid & 1;        // o-half
        float* row = l_s + (r >> 2) * kLSnl + (bc2 + (r & 3)) * kLSbp;
        float ex[5], ey[5];
        float sx = 0.f, sy = 0.f;
#pragma unroll
        for (int q = 0; q < 5; q++) {
          float2 t = *(const float2*)(row + (h * 5 + q) * 2);
          ex[q] = __expf(t.x); ey[q] = __expf(t.y);
          sx += ex[q]; sy += ey[q];
        }
        // combine the two o-halves (partner lane differs in bit 0)
        sx += __shfl_xor_sync(0xffffffffu, sx, 1);
        sy += __shfl_xor_sync(0xffffffffu, sy, 1);
        float ix = 1.f / sx, iy = 1.f / sy;
#pragma unroll
        for (int q = 0; q < 5; q++)
          *(float2*)(row + (h * 5 + q) * 2) = make_float2(ex[q] * ix, ey[q] * iy);
      }
      __syncthreads();
    }

    // weight by c (acc reused)
    u64 v16[16];
    if (MODE) {
      const float* cp = l_s + nl * kLSnl + bc2 * kLSbp + o * 2;
#pragma unroll
      for (int k = 0; k < 4; k++) {
        u64 c2 = *(const u64*)(cp + k * kLSbp);
#pragma unroll
        for (int j = 0; j < 4; j++) MUL2(v16[k * 4 + j], acc[k][j], c2);
      }
    } else {
#pragma unroll
      for (int k = 0; k < 4; k++)
#pragma unroll
        for (int j = 0; j < 4; j++) v16[k * 4 + j] = acc[k][j];
    }

    // reduce-scatter over nl (lane bits 0-2): 3 levels
    u64 v8[8];
    {
      const bool sel = (nl >> 2) & 1;
#pragma unroll
      for (int i = 0; i < 8; i++) {
        u64 send = sel ? v16[i] : v16[8 + i];
        u64 recv = __shfl_xor_sync(0xffffffffu, send, 4);
        u64 keep = sel ? v16[8 + i] : v16[i];
        ADD2(v8[i], keep, recv);
      }
    }
    u64 v4[4];
    {
      const bool sel = (nl >> 1) & 1;
#pragma unroll
      for (int i = 0; i < 4; i++) {
        u64 send = sel ? v8[i] : v8[4 + i];
        u64 recv = __shfl_xor_sync(0xffffffffu, send, 2);
        u64 keep = sel ? v8[4 + i] : v8[i];
        ADD2(v4[i], keep, recv);
      }
    }
    u64 v2[2];
    {
      const bool sel = nl & 1;
#pragma unroll
      for (int i = 0; i < 2; i++) {
        u64 send = sel ? v4[i] : v4[2 + i];
        u64 recv = __shfl_xor_sync(0xffffffffu, send, 1);
        u64 keep = sel ? v4[2 + i] : v4[i];
        ADD2(v2[i], keep, recv);
      }
    }
    {
      float l0, h0, l1, h1;
      UNPK2(l0, h0, v2[0]); UNPK2(l1, h1, v2[1]);
      float* dp = &g_part[((size_t)ng * kB + bca + 2 * kk) * kOE
                          + o * kE + eg * 4 + j0];
      *(float2*)dp         = make_float2(l0, l1);
      *(float2*)(dp + kOE) = make_float2(h0, h1);
    }
  }
}

// Reduce 144 partials + squash. 40960 items = blocks 0..127 exactly.
__device__ __forceinline__ void squash_phase(float* __restrict__ out,
                                             int mode, float scale, int tid) {
  if (blockIdx.x >= 128) return;
  int gt = blockIdx.x * kTH + tid;
  int h = gt & 3, eq = (gt >> 2) & 3, row = gt >> 4;  // row = b*10 + o
  const float* pp = g_part + (size_t)row * kE + eq * 4
                  + (size_t)(h * 36) * kB * kOE;
  float4 a = {0.f, 0.f, 0.f, 0.f};
#pragma unroll 4
  for (int p = 0; p < 36; p++) {
    float4 t = __ldcg((const float4*)(pp + (size_t)p * kB * kOE));
    a.x += t.x; a.y += t.y; a.z += t.z; a.w += t.w;
  }
  a.x += __shfl_xor_sync(0xffffffffu, a.x, 1);
  a.y += __shfl_xor_sync(0xffffffffu, a.y, 1);
  a.z += __shfl_xor_sync(0xffffffffu, a.z, 1);
  a.w += __shfl_xor_sync(0xffffffffu, a.w, 1);
  a.x += __shfl_xor_sync(0xffffffffu, a.x, 2);
  a.y += __shfl_xor_sync(0xffffffffu, a.y, 2);
  a.z += __shfl_xor_sync(0xffffffffu, a.z, 2);
  a.w += __shfl_xor_sync(0xffffffffu, a.w, 2);
  a.x *= scale; a.y *= scale; a.z *= scale; a.w *= scale;
  float n2 = a.x * a.x + a.y * a.y + a.z * a.z + a.w * a.w;
  n2 += __shfl_xor_sync(0xffffffffu, n2, 4);
  n2 += __shfl_xor_sync(0xffffffffu, n2, 8);
  float f = sqrtf(n2) / (1.f + n2);
  float4 v = make_float4(a.x * f, a.y * f, a.z * f, a.w * f);
  if (h == 0) {
    if (mode == 2) {
      *(float4*)(out + (size_t)row * kE + eq * 4) = v;
    } else if (mode == 1) {
      float4 old = *(const float4*)(g_vsum + (size_t)row * kE + eq * 4);
      v.x += old.x; v.y += old.y; v.z += old.z; v.w += old.w;
      *(float4*)(g_vsum + (size_t)row * kE + eq * 4) = v;
    } else {
      *(float4*)(g_vsum + (size_t)row * kE + eq * 4) = v;
    }
  }
}

__global__ void __launch_bounds__(kTH, 2) fused_kernel(
    const float* __restrict__ u_i,
    const float* __restrict__ W,
    const float* __restrict__ bias,
    float* __restrict__ out)
{
  extern __shared__ float sm[];
  float* u_s = sm;            // [nl(1028)][d(128)][b]
  float* l_s = sm + kOffL;    // [nl(1284)][b-pair(20)][o*2]

  const int tid = threadIdx.x;
  const int nl  = tid & 7;
  const int eg  = (tid >> 3) & 3;
  const int o   = tid >> 5;
  const int ng  = blockIdx.x >> 1;
  const int n0  = ng * kNL;
  const int bb0 = (blockIdx.x & 1) * kBH;

  // W slice + bias, once for all 3 iterations
  float w[kD][4];
  {
    const float* Wp = W + ((size_t)(n0 + nl) * kO + o) * (kD * kE) + eg * 4;
#pragma unroll
    for (int d = 0; d < kD; d++) {
      float4 w4 = *(const float4*)(Wp + d * kE);
      w[d][0] = w4.x; w[d][1] = w4.y; w[d][2] = w4.z; w[d][3] = w4.w;
    }
  }
  const float bv = bias[(n0 + nl) * kO + o];
  u64 bp; PACK2(bp, bv, bv);

  // stage u once for all 3 iterations: [b][n][d] -> [nl][d][b_local]
  for (int i = tid; i < kBH * kNL * 2; i += kTH) {
    int b = i >> 4, nl2 = (i >> 1) & 7, h = i & 1;
    float4 t = *(const float4*)(u_i + ((size_t)(bb0 + b) * kN + n0 + nl2) * kD + h * 4);
    float* du = u_s + nl2 * kUSnl + h * 4 * kUSd + b;
    du[0] = t.x; du[kUSd] = t.y; du[2 * kUSd] = t.z; du[3 * kUSd] = t.w;
  }
  __syncthreads();

  // iteration 1: uniform c (0.1 folded into squash scale)
  pass_phase<0>(u_s, l_s, tid, nl, eg, o, bb0, ng, w, bp);
  grid_barrier(tid);
  squash_phase(out, 0, 0.1f, tid);   // g_vsum = v1
  grid_barrier(tid);

  // iteration 2
  pass_phase<1>(u_s, l_s, tid, nl, eg, o, bb0, ng, w, bp);
  grid_barrier(tid);
  squash_phase(out, 1, 1.0f, tid);   // g_vsum = v1 + v2
  grid_barrier(tid);

  // iteration 3
  pass_phase<1>(u_s, l_s, tid, nl, eg, o, bb0, ng, w, bp);
  grid_barrier(tid);
  squash_phase(out, 2, 1.0f, tid);   // out = v3
}

extern "C" void kernel_launch(void* const* d_in, const int* in_sizes, int n_in,
                              void* d_out, int out_size) {
  const float* u    = (const float*)d_in[0];
  const float* W    = (const float*)d_in[1];
  const float* bias = (const float*)d_in[2];
  float* out = (float*)d_out;

  cudaFuncSetAttribute((const void*)fused_kernel,
                       cudaFuncAttributeMaxDynamicSharedMemorySize, kSmemBytes);

  fused_kernel<<<kGrid, kTH, kSmemBytes>>>(u, W, bias, out);
}